// round 17
// baseline (speedup 1.0000x reference)
#include <cuda_runtime.h>

#define MB   8
#define NN   512
#define HH   128
#define MTAB 128
#define RPB  8             // pos rows per pair block (= warps per block)
#define TPB  256
#define BLKX (NN / RPB)    // 64 blocks per batch; total pair blocks = 512

#define SMIN_C (-2.99573227355399f)   /* log(0.05) */
#define SMAX_C ( 3.46573590279973f)   /* log(32)   */
#define DS_C    ((SMAX_C - SMIN_C) / (float)(MTAB - 1))
#define INVDS_C ((float)(MTAB - 1) / (SMAX_C - SMIN_C))

__device__ float        g_table[MTAB];
__device__ double       g_part[MB * BLKX];
__device__ volatile int g_flag;        // table-ready flag (0 at launch, reset at end)
__device__ int          g_cnt_build;   // builder completion counter
__device__ int          g_cnt_pair;    // pair-block completion counter

// ---------------------------------------------------------------------------
// ONE fused kernel. Grid = (BLKX, MB) = 512 blocks of 256 threads.
//   phase A (blocks 0..MTAB-1 only): compute table point flat_bid exactly
//           (3->128->128->1 silu MLP at r = exp(s_p)), publish via flag.
//           All 512 blocks fit in one wave and builders occupy the first-148
//           bid slots (one per SM), so the spin-wait cannot deadlock.
//   phase B (all blocks): stage pos (before spin), spin on flag, stage
//           Catmull-Rom coefficients, evaluate 8 rows x 512 cols of pairs,
//           write per-block double partial.
//   phase C (last block): deterministic fixed-order finalize, 1 warp/batch;
//           subtract N*tab[0] diagonal, scale 0.5, reset sync state.
// ---------------------------------------------------------------------------
__global__ void fused_kernel(const float* __restrict__ pos,
                             const float* __restrict__ W1, const float* __restrict__ b1,
                             const float* __restrict__ W2, const float* __restrict__ b2,
                             const float* __restrict__ W3, const float* __restrict__ b3,
                             float* __restrict__ out) {
    __shared__ float  px[NN], py[NN], pz[NN];       // 6 KB
    __shared__ float4 coef[MTAB];                   // 2 KB
    __shared__ float  h1s[HH];                      // 512 B (build)
    __shared__ float4 part4[4][HH / 4];             // 2 KB (build)
    __shared__ float  wsum[4];
    __shared__ double dred[TPB / 32];
    __shared__ int    is_last;

    const int bx   = blockIdx.x, b = blockIdx.y;
    const int flat = b * BLKX + bx;
    const int tid  = threadIdx.x;
    const int lane = tid & 31, warp = tid >> 5;

    // ---- stage positions first (overlaps with table build on other SMs) ----
    const float* P = pos + (size_t)b * NN * 3;
    for (int i = tid; i < NN; i += TPB) {
        px[i] = P[3 * i + 0];
        py[i] = P[3 * i + 1];
        pz[i] = P[3 * i + 2];
    }

    // ---- phase A: builder blocks compute one table point ----
    if (flat < MTAB) {
        if (tid < HH) {
            float s = SMIN_C + (float)flat * DS_C;
            float r = __expf(s);
            float u = __expf(-s);
            float a = fmaf(r, W1[tid], fmaf(u, W1[HH + tid],
                        fmaf(u * u, W1[2 * HH + tid], b1[tid])));
            h1s[tid] = a / (1.0f + __expf(-a));     // silu(layer1)
        }
        __syncthreads();
        if (tid < HH) {
            const int kg = warp;                    // 0..3: k-group
            const int t4 = lane;                    // output quad
            const float4* __restrict__ W2v = reinterpret_cast<const float4*>(W2);
            float a0 = 0.f, a1 = 0.f, a2 = 0.f, a3 = 0.f;
#pragma unroll 8
            for (int kk = 0; kk < 32; ++kk) {
                const int k = kg * 32 + kk;
                float  h = h1s[k];                  // warp-uniform broadcast
                float4 w = W2v[k * 32 + t4];        // coalesced LDG.128
                a0 = fmaf(h, w.x, a0);
                a1 = fmaf(h, w.y, a1);
                a2 = fmaf(h, w.z, a2);
                a3 = fmaf(h, w.w, a3);
            }
            part4[kg][t4] = make_float4(a0, a1, a2, a3);
        }
        __syncthreads();
        if (tid < HH) {
            const float* pf = reinterpret_cast<const float*>(part4);
            float acc = pf[0 * HH + tid] + pf[1 * HH + tid]
                      + pf[2 * HH + tid] + pf[3 * HH + tid];
            float av  = acc + b2[tid];
            float h2  = av / (1.0f + __expf(-av));  // silu(layer2)
            float v   = h2 * W3[tid];
#pragma unroll
            for (int o = 16; o > 0; o >>= 1) v += __shfl_xor_sync(0xffffffffu, v, o);
            if (lane == 0) wsum[warp] = v;
        }
        __syncthreads();
        if (tid == 0) {
            g_table[flat] = wsum[0] + wsum[1] + wsum[2] + wsum[3] + b3[0];
            __threadfence();
            if (atomicAdd(&g_cnt_build, 1) == MTAB - 1)
                g_flag = 1;                          // release: table ready
        }
    }

    // ---- wait for table, then stage Catmull-Rom coefficients ----
    if (tid == 0) { while (g_flag == 0) { } __threadfence(); }
    __syncthreads();
    if (tid < MTAB) {
        const int i = tid;
        int   im = (i > 0) ? i - 1 : 0;
        int   i1 = (i + 1 < MTAB) ? i + 1 : MTAB - 1;
        int   ip = (i + 2 < MTAB) ? i + 2 : MTAB - 1;
        float p0 = g_table[im], p1 = g_table[i], p2 = g_table[i1], p3 = g_table[ip];
        float c1 = 0.5f * (p2 - p0);
        float c2 = fmaf(2.0f, p2, p0) - fmaf(2.5f, p1, 0.5f * p3);
        float c3 = fmaf(0.5f, p3 - p0, 1.5f * (p1 - p2));
        coef[i] = make_float4(p1, c1, c2, c3);
    }
    __syncthreads();

    // ---- phase B: 8 rows x 512 cols of pairs ----
    const int   i  = bx * RPB + warp;
    const float xi = px[i], yi = py[i], zi = pz[i];
    double acc0 = 0.0, acc1 = 0.0;                  // 2 chains: break DADD RAW
#pragma unroll 4
    for (int jj = 0; jj < NN; jj += 64) {
#pragma unroll
        for (int half = 0; half < 2; ++half) {
            const int j = jj + half * 32 + lane;
            float dx = xi - px[j], dy = yi - py[j], dz = zi - pz[j];
            float d2 = fmaf(dx, dx, fmaf(dy, dy, dz * dz));
            d2 = fmaxf(d2, 0.0025f);                 // r = max(dist, 0.05)
            float s = 0.5f * __logf(d2);             // log r (no sqrt)
            float x = (s - SMIN_C) * INVDS_C;
            x = fminf(fmaxf(x, 0.0f), (float)(MTAB - 1) - 0.002f);
            int   i0 = (int)x;
            float t  = x - (float)i0;
            float4 c = coef[i0];                     // one LDS.128
            float v  = fmaf(fmaf(fmaf(c.w, t, c.z), t, c.y), t, c.x);
            if (half == 0) acc0 += (double)v; else acc1 += (double)v;
        }
    }
    double acc = acc0 + acc1;
#pragma unroll
    for (int o = 16; o > 0; o >>= 1)
        acc += __shfl_xor_sync(0xffffffffu, acc, o);
    if (lane == 0) dred[warp] = acc;
    __syncthreads();

    if (tid == 0) {
        double tot = 0.0;
#pragma unroll
        for (int w = 0; w < TPB / 32; ++w) tot += dred[w];
        g_part[flat] = tot;
        __threadfence();
        is_last = (atomicAdd(&g_cnt_pair, 1) == BLKX * MB - 1);
    }
    __syncthreads();

    // ---- phase C: last block finalizes deterministically ----
    if (is_last) {
        const int bb = warp;                         // 8 warps = 8 batches
        double a2 = g_part[bb * BLKX + lane] + g_part[bb * BLKX + 32 + lane];
#pragma unroll
        for (int o = 16; o > 0; o >>= 1)
            a2 += __shfl_xor_sync(0xffffffffu, a2, o);
        if (lane == 0) {
            a2 -= (double)NN * (double)g_table[0];   // remove diagonal terms
            out[bb] = (float)(0.5 * a2);
        }
        __syncthreads();
        if (tid == 0) {                              // reset for next graph replay
            g_cnt_build = 0;
            g_cnt_pair  = 0;
            g_flag      = 0;
        }
    }
}

extern "C" void kernel_launch(void* const* d_in, const int* in_sizes, int n_in,
                              void* d_out, int out_size) {
    (void)in_sizes; (void)n_in; (void)out_size;
    const float* pos = (const float*)d_in[0];
    const float* W1  = (const float*)d_in[1];
    const float* b1  = (const float*)d_in[2];
    const float* W2  = (const float*)d_in[3];
    const float* b2  = (const float*)d_in[4];
    const float* W3  = (const float*)d_in[5];
    const float* b3  = (const float*)d_in[6];

    dim3 grid(BLKX, MB);
    fused_kernel<<<grid, TPB>>>(pos, W1, b1, W2, b2, W3, b3, (float*)d_out);
}